// round 1
// baseline (speedup 1.0000x reference)
#include <cuda_runtime.h>

#define CB    2
#define CS    2048
#define CDIM  2048
#define CH    16
#define CQL   1536
#define CKVL  512
#define CKD   576            // 512 + 64 rope
#define CROWS (CB * CS)      // 4096
#define ATT_SCALE 0.07216878364870323f   // 192^-0.5

// ---------------- scratch (device globals, no runtime alloc) ----------------
__device__ float g_q1[(size_t)CROWS * CQL];          // x @ wq_a^T, then rmsnorm
__device__ float g_kv[(size_t)CROWS * CKD];          // processed K' = [rms(kv_c), rope(k_pe)]
__device__ float g_kt[(size_t)CB * CKD * CS];        // K' transposed: [b][d][t]
__device__ float g_q2[(size_t)CROWS * CH * 192];     // q after wq_b
__device__ float g_qp[(size_t)CROWS * CH * CKD];     // Q' = [q_abs(512), rope(q_pe)(64)] per head
__device__ float g_oc[(size_t)CROWS * CH * 512];     // attention output in latent space
__device__ float g_ov[(size_t)CROWS * CH * 128];     // after w_v

// ---------------- generic tiled SGEMM: C[m,n] = sum_k A[m,k] * B(k,n) -------
// B(k,n) = Bm[k*sbk + n*sbn]  (handles both W[n,k] (NT) and W[k,n] (NN))
// blockIdx.z batches with element strides strA/strB/strC.
__global__ __launch_bounds__(256) void gemm128(
    const float* __restrict__ A, int lda, long long strA,
    const float* __restrict__ Bm, long long sbk, long long sbn, long long strB,
    float* __restrict__ C, int ldc, long long strC,
    int M, int N, int K)
{
    A  += (long long)blockIdx.z * strA;
    Bm += (long long)blockIdx.z * strB;
    C  += (long long)blockIdx.z * strC;

    __shared__ float As[8][132];
    __shared__ float Bs[8][132];

    int tid = threadIdx.x;
    int tx = tid & 15, ty = tid >> 4;
    int m0 = blockIdx.y * 128, n0 = blockIdx.x * 128;

    float acc[8][8];
#pragma unroll
    for (int i = 0; i < 8; i++)
#pragma unroll
        for (int j = 0; j < 8; j++) acc[i][j] = 0.f;

    for (int k0 = 0; k0 < K; k0 += 8) {
        // A tile (A is always k-contiguous row-major here)
#pragma unroll
        for (int j = 0; j < 4; j++) {
            int i = tid + j * 256;
            int kk = i & 7, r = i >> 3;
            As[kk][r] = A[(long long)(m0 + r) * lda + (k0 + kk)];
        }
        // B tile: pick coalesced mapping based on which stride is 1
        if (sbn == 1) {
#pragma unroll
            for (int j = 0; j < 4; j++) {
                int i = tid + j * 256;
                int n = i & 127, kk = i >> 7;
                int gn = n0 + n;
                Bs[kk][n] = (gn < N) ? Bm[(long long)(k0 + kk) * sbk + gn] : 0.f;
            }
        } else {
#pragma unroll
            for (int j = 0; j < 4; j++) {
                int i = tid + j * 256;
                int kk = i & 7, n = i >> 3;
                int gn = n0 + n;
                Bs[kk][n] = (gn < N) ? Bm[(long long)(k0 + kk) * sbk + (long long)gn * sbn] : 0.f;
            }
        }
        __syncthreads();
#pragma unroll
        for (int kk = 0; kk < 8; kk++) {
            float4 a0 = *(const float4*)&As[kk][ty * 8];
            float4 a1 = *(const float4*)&As[kk][ty * 8 + 4];
            float4 b0 = *(const float4*)&Bs[kk][tx * 8];
            float4 b1 = *(const float4*)&Bs[kk][tx * 8 + 4];
            float av[8] = {a0.x, a0.y, a0.z, a0.w, a1.x, a1.y, a1.z, a1.w};
            float bv[8] = {b0.x, b0.y, b0.z, b0.w, b1.x, b1.y, b1.z, b1.w};
#pragma unroll
            for (int i = 0; i < 8; i++)
#pragma unroll
                for (int j = 0; j < 8; j++)
                    acc[i][j] += av[i] * bv[j];
        }
        __syncthreads();
    }
#pragma unroll
    for (int i = 0; i < 8; i++) {
        int gm = m0 + ty * 8 + i;
#pragma unroll
        for (int j = 0; j < 8; j++) {
            int gn = n0 + tx * 8 + j;
            if (gn < N) C[(long long)gm * ldc + gn] = acc[i][j];
        }
    }
}

// ---------------- rmsnorm over rows of width n (in-place) -------------------
__global__ void rmsnorm_rows(float* __restrict__ x, const float* __restrict__ w, int n)
{
    long long row = blockIdx.x;
    float* r = x + row * n;
    float ss = 0.f;
    for (int i = threadIdx.x; i < n; i += 256) { float v = r[i]; ss += v * v; }
    __shared__ float red[8];
#pragma unroll
    for (int o = 16; o; o >>= 1) ss += __shfl_down_sync(0xffffffffu, ss, o);
    if ((threadIdx.x & 31) == 0) red[threadIdx.x >> 5] = ss;
    __syncthreads();
    if (threadIdx.x < 32) {
        float v = (threadIdx.x < 8) ? red[threadIdx.x] : 0.f;
#pragma unroll
        for (int o = 4; o; o >>= 1) v += __shfl_down_sync(0xffffffffu, v, o);
        if (threadIdx.x == 0) red[0] = v;
    }
    __syncthreads();
    float scale = rsqrtf(red[0] / (float)n + 1e-6f);
    for (int i = threadIdx.x; i < n; i += 256) r[i] = r[i] * scale * w[i];
}

// -------- kv row processing: rmsnorm first 512 (+w), rope last 64 -----------
__global__ void kv_process(float* __restrict__ kv, const float* __restrict__ w,
                           const float* __restrict__ cosp, const float* __restrict__ sinp)
{
    int row = blockIdx.x;
    int s = row % CS;
    float* r = kv + (long long)row * CKD;
    float ss = 0.f;
    for (int i = threadIdx.x; i < 512; i += 128) { float v = r[i]; ss += v * v; }
    __shared__ float red[4];
#pragma unroll
    for (int o = 16; o; o >>= 1) ss += __shfl_down_sync(0xffffffffu, ss, o);
    if ((threadIdx.x & 31) == 0) red[threadIdx.x >> 5] = ss;
    __syncthreads();
    float tot = red[0] + red[1] + red[2] + red[3];
    float scale = rsqrtf(tot / 512.f + 1e-6f);
    for (int i = threadIdx.x; i < 512; i += 128) r[i] = r[i] * scale * w[i];
    if (threadIdx.x < 32) {
        int i = threadIdx.x;
        float x0 = r[512 + 2 * i], x1 = r[512 + 2 * i + 1];
        float c = cosp[s * 32 + i], sn = sinp[s * 32 + i];
        r[512 + 2 * i]     = x0 * c - x1 * sn;
        r[512 + 2 * i + 1] = x0 * sn + x1 * c;
    }
}

// ---------------- K' transpose: kv[(b*S+t)*576 + d] -> kt[b][d][t] ----------
__global__ void transpose_kt(const float* __restrict__ kv, float* __restrict__ kt)
{
    __shared__ float tile[32][33];
    int bb = blockIdx.z;
    int d0 = blockIdx.x * 32, t0 = blockIdx.y * 32;
    int x = threadIdx.x, y = threadIdx.y;
#pragma unroll
    for (int j = 0; j < 32; j += 8)
        tile[y + j][x] = kv[((long long)(bb * CS + t0 + y + j)) * CKD + d0 + x];
    __syncthreads();
#pragma unroll
    for (int j = 0; j < 32; j += 8)
        kt[(long long)bb * CKD * CS + (long long)(d0 + y + j) * CS + (t0 + x)] = tile[x][y + j];
}

// ---------------- RoPE on q_pe: q2[row, h*192+128..192) -> qp[row, h*576+512..576)
__global__ void rope_q(const float* __restrict__ q2, float* __restrict__ qp,
                       const float* __restrict__ cosp, const float* __restrict__ sinp)
{
    int idx = blockIdx.x * 256 + threadIdx.x;
    if (idx >= CROWS * CH * 32) return;
    int i = idx & 31;
    int h = (idx >> 5) & 15;
    int row = idx >> 9;
    int s = row % CS;
    const float* src = q2 + (long long)row * 3072 + h * 192 + 128 + 2 * i;
    float x0 = src[0], x1 = src[1];
    float c = cosp[s * 32 + i], sn = sinp[s * 32 + i];
    float* dst = qp + (long long)row * 9216 + h * 576 + 512 + 2 * i;
    dst[0] = x0 * c - x1 * sn;
    dst[1] = x0 * sn + x1 * c;
}

// ---------------- fused causal attention, 8 queries per CTA -----------------
// shared: q_sh[8][576]  +  p_sh[8][2048]  = 83968 B
__global__ __launch_bounds__(256) void attn_kernel(
    const float* __restrict__ qp, const float* __restrict__ kt,
    const float* __restrict__ kv, float* __restrict__ oc)
{
    extern __shared__ float sm[];
    float* q_sh = sm;               // 8*576
    float* p_sh = sm + 8 * 576;     // 8*2048
    int tid = threadIdx.x;
    int q0 = (gridDim.x - 1 - blockIdx.x) * 8;   // heavy tiles first
    int h = blockIdx.y, bb = blockIdx.z;

    for (int i = tid; i < 8 * 576; i += 256) {
        int q = i / 576, d = i - q * 576;
        q_sh[i] = qp[((long long)(bb * CS + q0 + q)) * 9216 + h * 576 + d];
    }
    __syncthreads();

    int nT = q0 + 8;                // keys 0..q0+7
    const float* ktb = kt + (long long)bb * CKD * CS;

    // pass 1: scores
    for (int t0 = 0; t0 < nT; t0 += 256) {
        int t = t0 + tid;
        float acc[8] = {0, 0, 0, 0, 0, 0, 0, 0};
#pragma unroll 4
        for (int d = 0; d < CKD; d++) {
            float kvv = ktb[(long long)d * CS + t];
#pragma unroll
            for (int q = 0; q < 8; q++)
                acc[q] += kvv * q_sh[q * 576 + d];
        }
#pragma unroll
        for (int q = 0; q < 8; q++)
            p_sh[q * 2048 + t] = (t <= q0 + q) ? acc[q] * ATT_SCALE : -1e30f;
    }
    __syncthreads();

    // softmax: warp w handles query w, over all nT slots (masked -> 0)
    {
        int w = tid >> 5, lane = tid & 31;
        float* pr = p_sh + w * 2048;
        float m = -1e30f;
        for (int t = lane; t < nT; t += 32) m = fmaxf(m, pr[t]);
#pragma unroll
        for (int o = 16; o; o >>= 1) m = fmaxf(m, __shfl_xor_sync(0xffffffffu, m, o));
        float sum = 0.f;
        for (int t = lane; t < nT; t += 32) { float e = __expf(pr[t] - m); pr[t] = e; sum += e; }
#pragma unroll
        for (int o = 16; o; o >>= 1) sum += __shfl_xor_sync(0xffffffffu, sum, o);
        float inv = 1.f / sum;
        for (int t = lane; t < nT; t += 32) pr[t] *= inv;
    }
    __syncthreads();

    // pass 2: O = P @ kv_c ; thread owns columns c0, c1
    int c0 = tid, c1 = tid + 256;
    float o0[8] = {0, 0, 0, 0, 0, 0, 0, 0};
    float o1[8] = {0, 0, 0, 0, 0, 0, 0, 0};
    const float* kvb = kv + (long long)bb * CS * CKD;
    for (int t = 0; t < nT; t++) {
        float v0 = kvb[(long long)t * CKD + c0];
        float v1 = kvb[(long long)t * CKD + c1];
#pragma unroll
        for (int q = 0; q < 8; q++) {
            float pq = p_sh[q * 2048 + t];
            o0[q] += pq * v0;
            o1[q] += pq * v1;
        }
    }
#pragma unroll
    for (int q = 0; q < 8; q++) {
        long long orow = ((long long)(bb * CS + q0 + q)) * (CH * 512) + h * 512;
        oc[orow + c0] = o0[q];
        oc[orow + c1] = o1[q];
    }
}

// ---------------------------------------------------------------------------
extern "C" void kernel_launch(void* const* d_in, const int* in_sizes, int n_in,
                              void* d_out, int out_size)
{
    (void)in_sizes; (void)n_in; (void)out_size;
    const float* x        = (const float*)d_in[0];
    const float* wq_a     = (const float*)d_in[1];
    const float* q_norm_w = (const float*)d_in[2];
    const float* wq_b     = (const float*)d_in[3];
    const float* wkv_a    = (const float*)d_in[4];
    const float* kv_norm_w= (const float*)d_in[5];
    const float* wkv_b    = (const float*)d_in[6];
    const float* wo       = (const float*)d_in[7];
    const float* cosp     = (const float*)d_in[8];
    const float* sinp     = (const float*)d_in[9];
    float* out = (float*)d_out;

    float *q1, *kvb, *kt, *q2, *qp, *oc, *ov;
    cudaGetSymbolAddress((void**)&q1,  g_q1);
    cudaGetSymbolAddress((void**)&kvb, g_kv);
    cudaGetSymbolAddress((void**)&kt,  g_kt);
    cudaGetSymbolAddress((void**)&q2,  g_q2);
    cudaGetSymbolAddress((void**)&qp,  g_qp);
    cudaGetSymbolAddress((void**)&oc,  g_oc);
    cudaGetSymbolAddress((void**)&ov,  g_ov);

    // 1) q1 = x @ wq_a^T    [4096,1536] <- [4096,2048] x [1536,2048]
    gemm128<<<dim3(12, 32, 1), 256>>>(x, 2048, 0, wq_a, 1, 2048, 0,
                                      q1, 1536, 0, 4096, 1536, 2048);
    // 2) rmsnorm(q1)
    rmsnorm_rows<<<4096, 256>>>(q1, q_norm_w, 1536);
    // 3) kv = x @ wkv_a^T   [4096,576]
    gemm128<<<dim3(5, 32, 1), 256>>>(x, 2048, 0, wkv_a, 1, 2048, 0,
                                     kvb, 576, 0, 4096, 576, 2048);
    // 4) rmsnorm kv_c + rope k_pe  (in place)
    kv_process<<<4096, 128>>>(kvb, kv_norm_w, cosp, sinp);
    // 5) K' transpose -> [b][576][S]
    transpose_kt<<<dim3(18, 64, 2), dim3(32, 8)>>>(kvb, kt);
    // 6) q2 = q1 @ wq_b^T   [4096,3072]
    gemm128<<<dim3(24, 32, 1), 256>>>(q1, 1536, 0, wq_b, 1, 1536, 0,
                                      q2, 3072, 0, 4096, 3072, 1536);
    // 7) per-head q_abs = q_nope @ w_nope  (NN): into qp[:, h*576 .. +512)
    gemm128<<<dim3(4, 32, 16), 256>>>(q2, 3072, 192,
                                      wkv_b, 512, 1, 131072,
                                      qp, 9216, 576, 4096, 512, 128);
    // 8) rope(q_pe) -> qp[:, h*576+512 .. +576)
    rope_q<<<(CROWS * CH * 32) / 256, 256>>>(q2, qp, cosp, sinp);
    // 9) fused causal attention -> oc
    cudaFuncSetAttribute(attn_kernel, cudaFuncAttributeMaxDynamicSharedMemorySize, 83968);
    attn_kernel<<<dim3(256, 16, 2), 256, 83968>>>(qp, kt, kvb, oc);
    // 10) per-head o_v = oc @ w_v^T (NT): wkv_b[h] rows 128..256
    gemm128<<<dim3(1, 32, 16), 256>>>(oc, 8192, 512,
                                      wkv_b + 65536, 1, 512, 131072,
                                      ov, 2048, 128, 4096, 128, 512);
    // 11) out = ov @ wo^T   [4096,2048]
    gemm128<<<dim3(16, 32, 1), 256>>>(ov, 2048, 0, wo, 1, 2048, 0,
                                      out, 2048, 0, 4096, 2048, 2048);
}

// round 2
// speedup vs baseline: 5.3201x; 5.3201x over previous
#include <cuda_runtime.h>
#include <cstdint>

#define CB    2
#define CS    2048
#define CDIM  2048
#define CH    16
#define CQL   1536
#define CKVL  512
#define CKD   576
#define CROWS (CB * CS)
#define ATT_SCALE 0.07216878364870323f   // 192^-0.5

// ---------------- scratch (device globals) ----------------
__device__ __align__(256) float g_q1[(size_t)CROWS * CQL];
__device__ __align__(256) float g_kv[(size_t)CROWS * CKD];
__device__ __align__(256) float g_kt[(size_t)CB * CKD * CS];
__device__ __align__(256) float g_q2[(size_t)CROWS * CH * 192];
__device__ __align__(256) float g_qp[(size_t)CROWS * CH * CKD];
__device__ __align__(256) float g_oc[(size_t)CROWS * CH * 512];
__device__ __align__(256) float g_ov[(size_t)CROWS * CH * 128];
__device__ __align__(256) float g_p [(size_t)CB * CH * CS * CS];   // scores/probs
// pre-transposed weights
__device__ __align__(256) float g_wqat[(size_t)2048 * 1536];
__device__ __align__(256) float g_wkvat[(size_t)2048 * 576];
__device__ __align__(256) float g_wqbt[(size_t)1536 * 3072];
__device__ __align__(256) float g_wot [(size_t)2048 * 2048];
__device__ __align__(256) float g_wvt [(size_t)CH * 512 * 128];

// ---------------- helpers ----------------
__device__ __forceinline__ uint32_t cvt_tf32(float f) {
    uint32_t u;
    asm volatile("cvt.rna.tf32.f32 %0, %1;" : "=r"(u) : "f"(f));
    return u;
}
__device__ __forceinline__ void cp16(uint32_t saddr, const float* gptr) {
    asm volatile("cp.async.cg.shared.global [%0], [%1], 16;" :: "r"(saddr), "l"(gptr));
}
__device__ __forceinline__ void cp16z(uint32_t saddr, const float* gptr, int sz) {
    asm volatile("cp.async.cg.shared.global [%0], [%1], 16, %2;" :: "r"(saddr), "l"(gptr), "r"(sz));
}
__device__ __forceinline__ void mma_tf32(float* c, const uint32_t* a, uint32_t b0, uint32_t b1) {
    asm volatile(
        "mma.sync.aligned.m16n8k8.row.col.f32.tf32.tf32.f32 "
        "{%0,%1,%2,%3},{%4,%5,%6,%7},{%8,%9},{%0,%1,%2,%3};"
        : "+f"(c[0]), "+f"(c[1]), "+f"(c[2]), "+f"(c[3])
        : "r"(a[0]), "r"(a[1]), "r"(a[2]), "r"(a[3]), "r"(b0), "r"(b1));
}

// ---------------- tensor-core tf32 GEMM: C = A[M,K] @ B[K,N] ----------------
// 128x128x32 tiles, 8 warps (4x2), m16n8k8, cp.async double buffered.
// causal: skip tiles with bn > bm.  kclamp: K_eff = min(K, m0+128).
#define ALD 36
#define BLD 136
#define ABUF (128 * ALD)
#define BBUF (32 * BLD)

__global__ __launch_bounds__(256) void gemm_tc(
    const float* __restrict__ A, int lda, long long strA,
    const float* __restrict__ B, int ldb, long long strB,
    float* __restrict__ C, int ldc, long long strC,
    int M, int N, int K, int causal, int kclamp)
{
    int bm = blockIdx.y, bn = blockIdx.x;
    if (causal && bn > bm) return;
    A += (long long)blockIdx.z * strA;
    B += (long long)blockIdx.z * strB;
    C += (long long)blockIdx.z * strC;
    int m0 = bm * 128, n0 = bn * 128;
    int Keff = kclamp ? (K < m0 + 128 ? K : m0 + 128) : K;

    extern __shared__ float smem[];
    float* As = smem;                 // [2][128][36]
    float* Bs = smem + 2 * ABUF;      // [2][32][136]
    uint32_t sbase = (uint32_t)__cvta_generic_to_shared(smem);
    uint32_t sAs = sbase;
    uint32_t sBs = sbase + 2 * ABUF * 4;

    int tid = threadIdx.x;
    int wid = tid >> 5, lane = tid & 31;
    int wm = wid >> 1, wn = wid & 1;
    int g = lane >> 2, tg = lane & 3;

    float acc[2][8][4];
#pragma unroll
    for (int mi = 0; mi < 2; mi++)
#pragma unroll
        for (int j = 0; j < 8; j++)
#pragma unroll
            for (int r = 0; r < 4; r++) acc[mi][j][r] = 0.f;

    int ntk = Keff >> 5;   // Keff multiple of 32 in all uses

    auto load_tile = [&](int kt, int buf) {
        long long k0 = (long long)kt * 32;
#pragma unroll
        for (int i = 0; i < 4; i++) {
            int idx = tid + i * 256;
            int r = idx >> 3, c = (idx & 7) * 4;
            const float* gp = A + (long long)(m0 + r) * lda + k0 + c;
            cp16(sAs + (uint32_t)(buf * ABUF + r * ALD + c) * 4, gp);
        }
#pragma unroll
        for (int i = 0; i < 4; i++) {
            int idx = tid + i * 256;
            int kr = idx >> 5, c = (idx & 31) * 4;
            int gc = n0 + c;
            const float* gp = B + (k0 + kr) * (long long)ldb + (gc < N ? gc : 0);
            int sz = (gc < N) ? 16 : 0;
            cp16z(sBs + (uint32_t)(buf * BBUF + kr * BLD + c) * 4, gp, sz);
        }
        asm volatile("cp.async.commit_group;");
    };

    load_tile(0, 0);

    for (int kt = 0; kt < ntk; kt++) {
        int buf = kt & 1;
        if (kt + 1 < ntk) {
            load_tile(kt + 1, buf ^ 1);
            asm volatile("cp.async.wait_group 1;");
        } else {
            asm volatile("cp.async.wait_group 0;");
        }
        __syncthreads();

        const float* Asb = As + buf * ABUF;
        const float* Bsb = Bs + buf * BBUF;
#pragma unroll
        for (int ks = 0; ks < 4; ks++) {
            int kk = ks * 8;
            uint32_t a[2][4];
#pragma unroll
            for (int mi = 0; mi < 2; mi++) {
                int r = wm * 32 + mi * 16 + g;
                a[mi][0] = cvt_tf32(Asb[r * ALD + kk + tg]);
                a[mi][1] = cvt_tf32(Asb[(r + 8) * ALD + kk + tg]);
                a[mi][2] = cvt_tf32(Asb[r * ALD + kk + tg + 4]);
                a[mi][3] = cvt_tf32(Asb[(r + 8) * ALD + kk + tg + 4]);
            }
#pragma unroll
            for (int j = 0; j < 8; j++) {
                int c = wn * 64 + j * 8 + g;
                uint32_t b0 = cvt_tf32(Bsb[(kk + tg) * BLD + c]);
                uint32_t b1 = cvt_tf32(Bsb[(kk + tg + 4) * BLD + c]);
                mma_tf32(acc[0][j], a[0], b0, b1);
                mma_tf32(acc[1][j], a[1], b0, b1);
            }
        }
        __syncthreads();
    }

    // epilogue
#pragma unroll
    for (int mi = 0; mi < 2; mi++) {
#pragma unroll
        for (int j = 0; j < 8; j++) {
            int row = m0 + wm * 32 + mi * 16 + g;
            int col = n0 + wn * 64 + j * 8 + 2 * tg;
            if (col < N) {
                float2 v0 = make_float2(acc[mi][j][0], acc[mi][j][1]);
                float2 v1 = make_float2(acc[mi][j][2], acc[mi][j][3]);
                *(float2*)&C[(long long)row * ldc + col] = v0;
                *(float2*)&C[(long long)(row + 8) * ldc + col] = v1;
            }
        }
    }
}

// ---------------- generic batched 32x32 transpose: src[R,C] -> dst[C,R] -----
__global__ void transpose_g(const float* __restrict__ src, float* __restrict__ dst,
                            int R, int C, long long sstr, long long dstr)
{
    __shared__ float tile[32][33];
    src += (long long)blockIdx.z * sstr;
    dst += (long long)blockIdx.z * dstr;
    int c0 = blockIdx.x * 32, r0 = blockIdx.y * 32;
    int x = threadIdx.x, y = threadIdx.y;
#pragma unroll
    for (int j = 0; j < 32; j += 8)
        tile[y + j][x] = src[(long long)(r0 + y + j) * C + c0 + x];
    __syncthreads();
#pragma unroll
    for (int j = 0; j < 32; j += 8)
        dst[(long long)(c0 + y + j) * R + r0 + x] = tile[x][y + j];
}

// ---------------- rmsnorm over rows of width n (in-place) -------------------
__global__ void rmsnorm_rows(float* __restrict__ x, const float* __restrict__ w, int n)
{
    long long row = blockIdx.x;
    float* r = x + row * n;
    float ss = 0.f;
    for (int i = threadIdx.x; i < n; i += 256) { float v = r[i]; ss += v * v; }
    __shared__ float red[8];
#pragma unroll
    for (int o = 16; o; o >>= 1) ss += __shfl_down_sync(0xffffffffu, ss, o);
    if ((threadIdx.x & 31) == 0) red[threadIdx.x >> 5] = ss;
    __syncthreads();
    if (threadIdx.x < 32) {
        float v = (threadIdx.x < 8) ? red[threadIdx.x] : 0.f;
#pragma unroll
        for (int o = 4; o; o >>= 1) v += __shfl_down_sync(0xffffffffu, v, o);
        if (threadIdx.x == 0) red[0] = v;
    }
    __syncthreads();
    float scale = rsqrtf(red[0] / (float)n + 1e-6f);
    for (int i = threadIdx.x; i < n; i += 256) r[i] = r[i] * scale * w[i];
}

// -------- kv row processing: rmsnorm first 512 (+w), rope last 64 -----------
__global__ void kv_process(float* __restrict__ kv, const float* __restrict__ w,
                           const float* __restrict__ cosp, const float* __restrict__ sinp)
{
    int row = blockIdx.x;
    int s = row % CS;
    float* r = kv + (long long)row * CKD;
    float ss = 0.f;
    for (int i = threadIdx.x; i < 512; i += 128) { float v = r[i]; ss += v * v; }
    __shared__ float red[4];
#pragma unroll
    for (int o = 16; o; o >>= 1) ss += __shfl_down_sync(0xffffffffu, ss, o);
    if ((threadIdx.x & 31) == 0) red[threadIdx.x >> 5] = ss;
    __syncthreads();
    float tot = red[0] + red[1] + red[2] + red[3];
    float scale = rsqrtf(tot / 512.f + 1e-6f);
    for (int i = threadIdx.x; i < 512; i += 128) r[i] = r[i] * scale * w[i];
    if (threadIdx.x < 32) {
        int i = threadIdx.x;
        float x0 = r[512 + 2 * i], x1 = r[512 + 2 * i + 1];
        float c = cosp[s * 32 + i], sn = sinp[s * 32 + i];
        r[512 + 2 * i]     = x0 * c - x1 * sn;
        r[512 + 2 * i + 1] = x0 * sn + x1 * c;
    }
}

// ---------------- K' transpose: kv[(b*S+t)*576 + d] -> kt[b][d][t] ----------
__global__ void transpose_kt(const float* __restrict__ kv, float* __restrict__ kt)
{
    __shared__ float tile[32][33];
    int bb = blockIdx.z;
    int d0 = blockIdx.x * 32, t0 = blockIdx.y * 32;
    int x = threadIdx.x, y = threadIdx.y;
#pragma unroll
    for (int j = 0; j < 32; j += 8)
        tile[y + j][x] = kv[((long long)(bb * CS + t0 + y + j)) * CKD + d0 + x];
    __syncthreads();
#pragma unroll
    for (int j = 0; j < 32; j += 8)
        kt[(long long)bb * CKD * CS + (long long)(d0 + y + j) * CS + (t0 + x)] = tile[x][y + j];
}

// ---------------- RoPE on q_pe -----------------------------------------------
__global__ void rope_q(const float* __restrict__ q2, float* __restrict__ qp,
                       const float* __restrict__ cosp, const float* __restrict__ sinp)
{
    int idx = blockIdx.x * 256 + threadIdx.x;
    if (idx >= CROWS * CH * 32) return;
    int i = idx & 31;
    int h = (idx >> 5) & 15;
    int row = idx >> 9;
    int s = row % CS;
    const float* src = q2 + (long long)row * 3072 + h * 192 + 128 + 2 * i;
    float x0 = src[0], x1 = src[1];
    float c = cosp[s * 32 + i], sn = sinp[s * 32 + i];
    float* dst = qp + (long long)row * 9216 + h * 576 + 512 + 2 * i;
    dst[0] = x0 * c - x1 * sn;
    dst[1] = x0 * sn + x1 * c;
}

// ---------------- causal masked softmax over P rows --------------------------
// row = (b*16+h)*2048 + s ; scales logits, softmax over t<=s, zeros t>s.
__global__ __launch_bounds__(256) void softmax_causal(float* __restrict__ P)
{
    int row = blockIdx.x;
    int s = row & (CS - 1);
    float* pr = P + (long long)row * CS;
    int tid = threadIdx.x;

    float v[8];
    float m = -1e30f;
#pragma unroll
    for (int i = 0; i < 8; i++) {
        int t = tid + i * 256;
        v[i] = (t <= s) ? pr[t] * ATT_SCALE : -1e30f;
        m = fmaxf(m, v[i]);
    }
    __shared__ float red[8];
#pragma unroll
    for (int o = 16; o; o >>= 1) m = fmaxf(m, __shfl_xor_sync(0xffffffffu, m, o));
    if ((tid & 31) == 0) red[tid >> 5] = m;
    __syncthreads();
    m = red[0];
#pragma unroll
    for (int w = 1; w < 8; w++) m = fmaxf(m, red[w]);

    float sum = 0.f;
#pragma unroll
    for (int i = 0; i < 8; i++) {
        int t = tid + i * 256;
        v[i] = (t <= s) ? __expf(v[i] - m) : 0.f;
        sum += v[i];
    }
    __syncthreads();
#pragma unroll
    for (int o = 16; o; o >>= 1) sum += __shfl_xor_sync(0xffffffffu, sum, o);
    if ((tid & 31) == 0) red[tid >> 5] = sum;
    __syncthreads();
    sum = 0.f;
#pragma unroll
    for (int w = 0; w < 8; w++) sum += red[w];
    float inv = 1.f / sum;
#pragma unroll
    for (int i = 0; i < 8; i++)
        pr[tid + i * 256] = v[i] * inv;
}

// ---------------------------------------------------------------------------
extern "C" void kernel_launch(void* const* d_in, const int* in_sizes, int n_in,
                              void* d_out, int out_size)
{
    (void)in_sizes; (void)n_in; (void)out_size;
    const float* x        = (const float*)d_in[0];
    const float* wq_a     = (const float*)d_in[1];
    const float* q_norm_w = (const float*)d_in[2];
    const float* wq_b     = (const float*)d_in[3];
    const float* wkv_a    = (const float*)d_in[4];
    const float* kv_norm_w= (const float*)d_in[5];
    const float* wkv_b    = (const float*)d_in[6];
    const float* wo       = (const float*)d_in[7];
    const float* cosp     = (const float*)d_in[8];
    const float* sinp     = (const float*)d_in[9];
    float* out = (float*)d_out;

    float *q1, *kvb, *kt, *q2, *qp, *oc, *ov, *P;
    float *wqat, *wkvat, *wqbt, *wot, *wvt;
    cudaGetSymbolAddress((void**)&q1,  g_q1);
    cudaGetSymbolAddress((void**)&kvb, g_kv);
    cudaGetSymbolAddress((void**)&kt,  g_kt);
    cudaGetSymbolAddress((void**)&q2,  g_q2);
    cudaGetSymbolAddress((void**)&qp,  g_qp);
    cudaGetSymbolAddress((void**)&oc,  g_oc);
    cudaGetSymbolAddress((void**)&ov,  g_ov);
    cudaGetSymbolAddress((void**)&P,   g_p);
    cudaGetSymbolAddress((void**)&wqat, g_wqat);
    cudaGetSymbolAddress((void**)&wkvat, g_wkvat);
    cudaGetSymbolAddress((void**)&wqbt, g_wqbt);
    cudaGetSymbolAddress((void**)&wot,  g_wot);
    cudaGetSymbolAddress((void**)&wvt,  g_wvt);

    const int SMEM = (2 * ABUF + 2 * BBUF) * 4;   // 71680
    static bool attr_set = false;
    cudaFuncSetAttribute(gemm_tc, cudaFuncAttributeMaxDynamicSharedMemorySize, SMEM);
    (void)attr_set;

    dim3 t32(32, 8);
    // weight transposes
    transpose_g<<<dim3(64, 48, 1), t32>>>(wq_a, wqat, 1536, 2048, 0, 0);
    transpose_g<<<dim3(64, 18, 1), t32>>>(wkv_a, wkvat, 576, 2048, 0, 0);
    transpose_g<<<dim3(48, 96, 1), t32>>>(wq_b, wqbt, 3072, 1536, 0, 0);
    transpose_g<<<dim3(64, 64, 1), t32>>>(wo, wot, 2048, 2048, 0, 0);
    transpose_g<<<dim3(16, 4, 16), t32>>>(wkv_b + 65536, wvt, 128, 512, 131072, 65536);

    // 1) q1 = x @ wq_a^T
    gemm_tc<<<dim3(12, 32, 1), 256, SMEM>>>(x, 2048, 0, wqat, 1536, 0,
                                            q1, 1536, 0, 4096, 1536, 2048, 0, 0);
    // 2) rmsnorm(q1)
    rmsnorm_rows<<<4096, 256>>>(q1, q_norm_w, 1536);
    // 3) kv = x @ wkv_a^T
    gemm_tc<<<dim3(5, 32, 1), 256, SMEM>>>(x, 2048, 0, wkvat, 576, 0,
                                           kvb, 576, 0, 4096, 576, 2048, 0, 0);
    // 4) rmsnorm kv_c + rope k_pe
    kv_process<<<4096, 128>>>(kvb, kv_norm_w, cosp, sinp);
    // 5) K' transpose
    transpose_kt<<<dim3(18, 64, 2), t32>>>(kvb, kt);
    // 6) q2 = q1 @ wq_b^T
    gemm_tc<<<dim3(24, 32, 1), 256, SMEM>>>(q1, 1536, 0, wqbt, 3072, 0,
                                            q2, 3072, 0, 4096, 3072, 1536, 0, 0);
    // 7) q_abs per head (z=16): q2[:,h,0:128] @ w_nope[h] -> qp[:,h,0:512]
    gemm_tc<<<dim3(4, 32, 16), 256, SMEM>>>(q2, 3072, 192, wkv_b, 512, 131072,
                                            qp, 9216, 576, 4096, 512, 128, 0, 0);
    // 8) rope q_pe -> qp[:,h,512:576]
    rope_q<<<(CROWS * CH * 32) / 256, 256>>>(q2, qp, cosp, sinp);
    // 9) scores per batch (z=h, causal skip)
    for (int b = 0; b < 2; b++) {
        gemm_tc<<<dim3(16, 16, 16), 256, SMEM>>>(
            qp + (long long)b * CS * 9216, 9216, 576,
            kt + (long long)b * CKD * CS, CS, 0,
            P + (long long)b * CH * CS * CS, CS, (long long)CS * CS,
            2048, 2048, 576, 1, 0);
    }
    // 10) softmax (scale + causal mask + normalize + zero upper)
    softmax_causal<<<CB * CH * CS, 256>>>(P);
    // 11) O = P @ kv_c  (z=h, K clamped to m0+128)
    for (int b = 0; b < 2; b++) {
        gemm_tc<<<dim3(4, 16, 16), 256, SMEM>>>(
            P + (long long)b * CH * CS * CS, CS, (long long)CS * CS,
            kvb + (long long)b * CS * CKD, CKD, 0,
            oc + (long long)b * CS * 8192 + 0, 8192, 512,
            2048, 512, 2048, 0, 1);
    }
    // 12) o_v per head (z=16): oc[:,h,:512] @ wvt[h] -> ov[:,h,:128]
    gemm_tc<<<dim3(1, 32, 16), 256, SMEM>>>(oc, 8192, 512, wvt, 128, 65536,
                                            ov, 2048, 128, 4096, 128, 512, 0, 0);
    // 13) out = ov @ wo^T
    gemm_tc<<<dim3(16, 32, 1), 256, SMEM>>>(ov, 2048, 0, wot, 2048, 0,
                                            out, 2048, 0, 4096, 2048, 2048, 0, 0);
}

// round 4
// speedup vs baseline: 5.8676x; 1.1029x over previous
#include <cuda_runtime.h>
#include <cstdint>

#define CS 2048
#define CH 16
#define ATT_SCALE 0.07216878364870323f   // 192^-0.5

// ---------------- scratch (device globals, fp32 pre-rounded to tf32) --------
__device__ __align__(256) float g_xr [(size_t)4096*2048];
__device__ __align__(256) float g_wqar[(size_t)1536*2048];
__device__ __align__(256) float g_wkvar[(size_t)576*2048];
__device__ __align__(256) float g_wqbr[(size_t)3072*1536];
__device__ __align__(256) float g_wor[(size_t)2048*2048];
__device__ __align__(256) float g_wvr[(size_t)16*128*512];
__device__ __align__(256) float g_wnt[(size_t)16*512*128];
__device__ __align__(256) float g_q1 [(size_t)4096*1536];
__device__ __align__(256) float g_kv [(size_t)4096*576];
__device__ __align__(256) float g_kt [(size_t)2*512*2048];
__device__ __align__(256) float g_q2 [(size_t)4096*3072];
__device__ __align__(256) float g_qp [(size_t)4096*9216];
__device__ __align__(256) float g_pf [(size_t)2*CH*CS*CS];
__device__ __align__(256) float g_oc [(size_t)4096*8192];
__device__ __align__(256) float g_ov [(size_t)4096*2048];

// ---------------- helpers ----------------
__device__ __forceinline__ float rne_tf32(float f) {
    uint32_t u;
    asm("cvt.rna.tf32.f32 %0, %1;" : "=r"(u) : "f"(f));
    return __uint_as_float(u);
}
__device__ __forceinline__ void cp16(uint32_t saddr, const void* gptr) {
    asm volatile("cp.async.cg.shared.global [%0], [%1], 16;" :: "r"(saddr), "l"(gptr));
}
__device__ __forceinline__ void cp16z(uint32_t saddr, const void* gptr, int sz) {
    asm volatile("cp.async.cg.shared.global [%0], [%1], 16, %2;" :: "r"(saddr), "l"(gptr), "r"(sz));
}
__device__ __forceinline__ void mma_tf32(float* c, const uint32_t* a, uint32_t b0, uint32_t b1) {
    asm volatile(
        "mma.sync.aligned.m16n8k8.row.col.f32.tf32.tf32.f32 "
        "{%0,%1,%2,%3},{%4,%5,%6,%7},{%8,%9},{%0,%1,%2,%3};"
        : "+f"(c[0]), "+f"(c[1]), "+f"(c[2]), "+f"(c[3])
        : "r"(a[0]), "r"(a[1]), "r"(a[2]), "r"(a[3]), "r"(b0), "r"(b1));
}

// ---------------- tensor-core tf32 GEMM: C[m,n] = sum_k A[m,k]*B[n,k] -------
// A: [M,K] k-major (lda). B: [N,K] k-major (ldb). Both PRE-ROUNDED to tf32.
// 128x128x32 tiles, 8 warps (4x2), m16n8k8, cp.async double buffered.
// causal: skip tiles bn > bm.  kclamp: Keff = min(K, m0+128). roundC: round out.
#define TLD 36
#define TBUF (128 * TLD)

__global__ __launch_bounds__(256, 2) void gemm_tc(
    const float* __restrict__ A, int lda, long long strA,
    const float* __restrict__ B, int ldb, long long strB,
    float* __restrict__ C, int ldc, long long strC,
    int M, int N, int K, int causal, int kclamp, int roundC)
{
    int bm = blockIdx.y, bn = blockIdx.x;
    if (causal && bn > bm) return;
    long long z = blockIdx.z;
    A += z * strA;
    B += z * strB;
    C += z * strC;
    int m0 = bm * 128, n0 = bn * 128;
    int Keff = kclamp ? (K < m0 + 128 ? K : m0 + 128) : K;
    int ntk = Keff >> 5;

    extern __shared__ float smem[];
    float* As = smem;                  // [2][128][36]
    float* Bs = smem + 2 * TBUF;       // [2][128][36]
    uint32_t sbase = (uint32_t)__cvta_generic_to_shared(smem);
    uint32_t sAs = sbase;
    uint32_t sBs = sbase + 2 * TBUF * 4;

    int tid = threadIdx.x;
    int wid = tid >> 5, lane = tid & 31;
    int wm = wid >> 1, wn = wid & 1;
    int g = lane >> 2, tg = lane & 3;

    float acc[2][8][4];
#pragma unroll
    for (int mi = 0; mi < 2; mi++)
#pragma unroll
        for (int j = 0; j < 8; j++)
#pragma unroll
            for (int r = 0; r < 4; r++) acc[mi][j][r] = 0.f;

    auto load_tile = [&](int kt, int buf) {
        long long k0 = (long long)kt * 32;
#pragma unroll
        for (int i = 0; i < 4; i++) {
            int idx = tid + i * 256;
            int row = idx >> 3, c8 = idx & 7;
            cp16(sAs + (uint32_t)(buf * TBUF + row * TLD + c8 * 4) * 4,
                 A + (long long)(m0 + row) * lda + k0 + c8 * 4);
        }
#pragma unroll
        for (int i = 0; i < 4; i++) {
            int idx = tid + i * 256;
            int row = idx >> 3, c8 = idx & 7;
            int gn = n0 + row;
            cp16z(sBs + (uint32_t)(buf * TBUF + row * TLD + c8 * 4) * 4,
                  B + (long long)(gn < N ? gn : 0) * ldb + k0 + c8 * 4,
                  gn < N ? 16 : 0);
        }
        asm volatile("cp.async.commit_group;" ::: "memory");
    };

    load_tile(0, 0);

    for (int kt = 0; kt < ntk; kt++) {
        int buf = kt & 1;
        if (kt + 1 < ntk) {
            load_tile(kt + 1, buf ^ 1);
            asm volatile("cp.async.wait_group 1;" ::: "memory");
        } else {
            asm volatile("cp.async.wait_group 0;" ::: "memory");
        }
        __syncthreads();

        const float* Asb = As + buf * TBUF;
        const float* Bsb = Bs + buf * TBUF;
#pragma unroll
        for (int ks = 0; ks < 4; ks++) {
            int kk = ks * 8;
            uint32_t a[2][4];
#pragma unroll
            for (int mi = 0; mi < 2; mi++) {
                int r = wm * 32 + mi * 16 + g;
                a[mi][0] = __float_as_uint(Asb[r * TLD + kk + tg]);
                a[mi][1] = __float_as_uint(Asb[(r + 8) * TLD + kk + tg]);
                a[mi][2] = __float_as_uint(Asb[r * TLD + kk + tg + 4]);
                a[mi][3] = __float_as_uint(Asb[(r + 8) * TLD + kk + tg + 4]);
            }
#pragma unroll
            for (int j = 0; j < 8; j++) {
                int c = wn * 64 + j * 8 + g;
                uint32_t b0 = __float_as_uint(Bsb[c * TLD + kk + tg]);
                uint32_t b1 = __float_as_uint(Bsb[c * TLD + kk + tg + 4]);
                mma_tf32(acc[0][j], a[0], b0, b1);
                mma_tf32(acc[1][j], a[1], b0, b1);
            }
        }
        __syncthreads();
    }

    // epilogue
#pragma unroll
    for (int mi = 0; mi < 2; mi++) {
#pragma unroll
        for (int j = 0; j < 8; j++) {
            int row = m0 + wm * 32 + mi * 16 + g;
            int col = n0 + wn * 64 + j * 8 + 2 * tg;
            if (col < N) {
                float v0 = acc[mi][j][0], v1 = acc[mi][j][1];
                float v2 = acc[mi][j][2], v3 = acc[mi][j][3];
                if (roundC) {
                    v0 = rne_tf32(v0); v1 = rne_tf32(v1);
                    v2 = rne_tf32(v2); v3 = rne_tf32(v3);
                }
                *(float2*)&C[(long long)row * ldc + col] = make_float2(v0, v1);
                *(float2*)&C[(long long)(row + 8) * ldc + col] = make_float2(v2, v3);
            }
        }
    }
}

// ---------------- prep: rounded copies / transposes --------------------------
__global__ void round_copy(const float* __restrict__ s, float* __restrict__ d, long long n4)
{
    long long i = (long long)blockIdx.x * 256 + threadIdx.x;
    if (i >= n4) return;
    float4 v = ((const float4*)s)[i];
    v.x = rne_tf32(v.x); v.y = rne_tf32(v.y);
    v.z = rne_tf32(v.z); v.w = rne_tf32(v.w);
    ((float4*)d)[i] = v;
}

// w_v slices: head h, src wkvb + h*131072 + 65536 + off (65536 each), rounded
__global__ void round_wv(const float* __restrict__ wkvb, float* __restrict__ d)
{
    long long i4 = (long long)blockIdx.x * 256 + threadIdx.x;   // float4 index
    long long head = i4 >> 14, off = (i4 & 16383) * 4;
    float4 v = *(const float4*)(wkvb + head * 131072 + 65536 + off);
    v.x = rne_tf32(v.x); v.y = rne_tf32(v.y);
    v.z = rne_tf32(v.z); v.w = rne_tf32(v.w);
    ((float4*)d)[i4] = v;
}

// transpose + round: per z, src[R][sld] (use C cols) -> dst[C][R]
__global__ void transpose_round(const float* __restrict__ src, float* __restrict__ dst,
                                int R, int C, int sld, long long sstr, long long dstr)
{
    __shared__ float tile[32][33];
    src += (long long)blockIdx.z * sstr;
    dst += (long long)blockIdx.z * dstr;
    int c0 = blockIdx.x * 32, r0 = blockIdx.y * 32;
    int x = threadIdx.x, y = threadIdx.y;
#pragma unroll
    for (int j = 0; j < 32; j += 8)
        tile[y + j][x] = src[(long long)(r0 + y + j) * sld + c0 + x];
    __syncthreads();
#pragma unroll
    for (int j = 0; j < 32; j += 8)
        dst[(long long)(c0 + y + j) * R + r0 + x] = rne_tf32(tile[x][y + j]);
}

// ---------------- rmsnorm rows (in-place, rounded stores) --------------------
__global__ void rmsnorm_rows(float* __restrict__ x, const float* __restrict__ w, int n)
{
    long long row = blockIdx.x;
    float* r = x + row * n;
    float ss = 0.f;
    for (int i = threadIdx.x; i < n; i += 256) { float v = r[i]; ss += v * v; }
    __shared__ float red[8];
#pragma unroll
    for (int o = 16; o; o >>= 1) ss += __shfl_xor_sync(0xffffffffu, ss, o);
    if ((threadIdx.x & 31) == 0) red[threadIdx.x >> 5] = ss;
    __syncthreads();
    float tot = 0.f;
#pragma unroll
    for (int wv = 0; wv < 8; wv++) tot += red[wv];
    float scale = rsqrtf(tot / (float)n + 1e-6f);
    for (int i = threadIdx.x; i < n; i += 256) r[i] = rne_tf32(r[i] * scale * w[i]);
}

// -------- kv row: rmsnorm first 512 (+w), rope last 64; rounded stores ------
__global__ void kv_process(float* __restrict__ kv, const float* __restrict__ w,
                           const float* __restrict__ cosp, const float* __restrict__ sinp)
{
    int row = blockIdx.x;
    int s = row % CS;
    float* r = kv + (long long)row * 576;
    float ss = 0.f;
    for (int i = threadIdx.x; i < 512; i += 128) { float v = r[i]; ss += v * v; }
    __shared__ float red[4];
#pragma unroll
    for (int o = 16; o; o >>= 1) ss += __shfl_xor_sync(0xffffffffu, ss, o);
    if ((threadIdx.x & 31) == 0) red[threadIdx.x >> 5] = ss;
    __syncthreads();
    float tot = red[0] + red[1] + red[2] + red[3];
    float scale = rsqrtf(tot / 512.f + 1e-6f);
    for (int i = threadIdx.x; i < 512; i += 128) r[i] = rne_tf32(r[i] * scale * w[i]);
    if (threadIdx.x < 32) {
        int i = threadIdx.x;
        float x0 = r[512 + 2 * i], x1 = r[512 + 2 * i + 1];
        float c = cosp[s * 32 + i], sn = sinp[s * 32 + i];
        r[512 + 2 * i]     = rne_tf32(x0 * c - x1 * sn);
        r[512 + 2 * i + 1] = rne_tf32(x0 * sn + x1 * c);
    }
}

// ---------------- RoPE on q_pe: q2 -> qp (rounded) ---------------------------
__global__ void rope_q(const float* __restrict__ q2, float* __restrict__ qp,
                       const float* __restrict__ cosp, const float* __restrict__ sinp)
{
    int idx = blockIdx.x * 256 + threadIdx.x;
    if (idx >= 4096 * CH * 32) return;
    int i = idx & 31;
    int h = (idx >> 5) & 15;
    int row = idx >> 9;
    int s = row % CS;
    const float* src = q2 + (long long)row * 3072 + h * 192 + 128 + 2 * i;
    float x0 = src[0], x1 = src[1];
    float c = cosp[s * 32 + i], sn = sinp[s * 32 + i];
    float* dst = qp + (long long)row * 9216 + h * 576 + 512 + 2 * i;
    dst[0] = rne_tf32(x0 * c - x1 * sn);
    dst[1] = rne_tf32(x0 * sn + x1 * c);
}

// ---------------- causal softmax over P rows (in-place, rounded) -------------
__global__ __launch_bounds__(256) void softmax_causal(float* __restrict__ P)
{
    int row = blockIdx.x;
    int s = row & (CS - 1);
    float* pr = P + (long long)row * CS;
    int tid = threadIdx.x;

    float v[8];
    float m = -1e30f;
#pragma unroll
    for (int i = 0; i < 8; i++) {
        int t = tid + i * 256;
        v[i] = (t <= s) ? pr[t] * ATT_SCALE : -1e30f;
        m = fmaxf(m, v[i]);
    }
    __shared__ float red[8];
#pragma unroll
    for (int o = 16; o; o >>= 1) m = fmaxf(m, __shfl_xor_sync(0xffffffffu, m, o));
    if ((tid & 31) == 0) red[tid >> 5] = m;
    __syncthreads();
    m = red[0];
#pragma unroll
    for (int w = 1; w < 8; w++) m = fmaxf(m, red[w]);

    float sum = 0.f;
#pragma unroll
    for (int i = 0; i < 8; i++) {
        int t = tid + i * 256;
        v[i] = (t <= s) ? __expf(v[i] - m) : 0.f;
        sum += v[i];
    }
    __syncthreads();
#pragma unroll
    for (int o = 16; o; o >>= 1) sum += __shfl_xor_sync(0xffffffffu, sum, o);
    if ((tid & 31) == 0) red[tid >> 5] = sum;
    __syncthreads();
    sum = 0.f;
#pragma unroll
    for (int w = 0; w < 8; w++) sum += red[w];
    float inv = 1.f / sum;
#pragma unroll
    for (int i = 0; i < 8; i++)
        pr[tid + i * 256] = rne_tf32(v[i] * inv);
}

// ---------------------------------------------------------------------------
extern "C" void kernel_launch(void* const* d_in, const int* in_sizes, int n_in,
                              void* d_out, int out_size)
{
    (void)in_sizes; (void)n_in; (void)out_size;
    const float* x        = (const float*)d_in[0];
    const float* wq_a     = (const float*)d_in[1];
    const float* q_norm_w = (const float*)d_in[2];
    const float* wq_b     = (const float*)d_in[3];
    const float* wkv_a    = (const float*)d_in[4];
    const float* kv_norm_w= (const float*)d_in[5];
    const float* wkv_b    = (const float*)d_in[6];
    const float* wo       = (const float*)d_in[7];
    const float* cosp     = (const float*)d_in[8];
    const float* sinp     = (const float*)d_in[9];
    float* out = (float*)d_out;

    float *xr, *wqar, *wkvar, *wqbr, *wor, *wvr, *wnt;
    float *q1, *kvb, *kt, *q2, *qp, *pf, *oc, *ov;
    cudaGetSymbolAddress((void**)&xr,   g_xr);
    cudaGetSymbolAddress((void**)&wqar, g_wqar);
    cudaGetSymbolAddress((void**)&wkvar,g_wkvar);
    cudaGetSymbolAddress((void**)&wqbr, g_wqbr);
    cudaGetSymbolAddress((void**)&wor,  g_wor);
    cudaGetSymbolAddress((void**)&wvr,  g_wvr);
    cudaGetSymbolAddress((void**)&wnt,  g_wnt);
    cudaGetSymbolAddress((void**)&q1,   g_q1);
    cudaGetSymbolAddress((void**)&kvb,  g_kv);
    cudaGetSymbolAddress((void**)&kt,   g_kt);
    cudaGetSymbolAddress((void**)&q2,   g_q2);
    cudaGetSymbolAddress((void**)&qp,   g_qp);
    cudaGetSymbolAddress((void**)&pf,   g_pf);
    cudaGetSymbolAddress((void**)&oc,   g_oc);
    cudaGetSymbolAddress((void**)&ov,   g_ov);

    const int SMEM = 4 * TBUF * 4;   // 73728
    cudaFuncSetAttribute(gemm_tc, cudaFuncAttributeMaxDynamicSharedMemorySize, SMEM);

    dim3 t32(32, 8);
    // ---- prep: round everything to tf32 once ----
    round_copy<<<8192, 256>>>(x,     xr,    2097152);
    round_copy<<<3072, 256>>>(wq_a,  wqar,  786432);
    round_copy<<<1152, 256>>>(wkv_a, wkvar, 294912);
    round_copy<<<4608, 256>>>(wq_b,  wqbr,  1179648);
    round_copy<<<4096, 256>>>(wo,    wor,   1048576);
    round_wv<<<1024, 256>>>(wkv_b, wvr);
    // w_nope^T per head: src [128][512] (sld 512) -> [512][128]
    transpose_round<<<dim3(16, 4, 16), t32>>>(wkv_b, wnt, 128, 512, 512, 131072, 65536);

    // 1) q1 = x @ wq_a^T
    gemm_tc<<<dim3(12, 32, 1), 256, SMEM>>>(xr, 2048, 0, wqar, 2048, 0,
        q1, 1536, 0, 4096, 1536, 2048, 0, 0, 0);
    // 2) rmsnorm q1 (rounds)
    rmsnorm_rows<<<4096, 256>>>(q1, q_norm_w, 1536);
    // 3) kv = x @ wkv_a^T
    gemm_tc<<<dim3(5, 32, 1), 256, SMEM>>>(xr, 2048, 0, wkvar, 2048, 0,
        kvb, 576, 0, 4096, 576, 2048, 0, 0, 0);
    // 4) rmsnorm kv_c + rope k_pe (rounds)
    kv_process<<<4096, 128>>>(kvb, kv_norm_w, cosp, sinp);
    // 5) kv_c^T per batch -> kt [b][512][2048]
    transpose_round<<<dim3(16, 64, 2), t32>>>(kvb, kt, 2048, 512, 576,
        (long long)2048 * 576, (long long)512 * 2048);
    // 6) q2 = q1 @ wq_b^T (rounded out)
    gemm_tc<<<dim3(24, 32, 1), 256, SMEM>>>(q1, 1536, 0, wqbr, 1536, 0,
        q2, 3072, 0, 4096, 3072, 1536, 0, 0, 1);
    // 7) q_abs per head: q2[:,h*192:+128] @ wnt[h]^T -> qp[:,h*576:+512] (rounded)
    gemm_tc<<<dim3(4, 32, 16), 256, SMEM>>>(q2, 3072, 192, wnt, 128, 65536,
        qp, 9216, 576, 4096, 512, 128, 0, 0, 1);
    // 8) rope q_pe -> qp[:,h*576+512:+64] (rounded)
    rope_q<<<8192, 256>>>(q2, qp, cosp, sinp);
    // 9) scores per (b,h): P = Q' @ K'^T, causal tile skip
    for (int b = 0; b < 2; b++) {
        gemm_tc<<<dim3(16, 16, 16), 256, SMEM>>>(
            qp + (long long)b * CS * 9216, 9216, 576,
            kvb + (long long)b * CS * 576, 576, 0,
            pf + (long long)b * CH * CS * CS, CS, (long long)CS * CS,
            2048, 2048, 576, 1, 0, 0);
    }
    // 10) softmax in-place (rounds)
    softmax_causal<<<2 * CH * CS, 256>>>(pf);
    // 11) O = P @ kv_c^T' (K clamped to m0+128, rounded out)
    for (int b = 0; b < 2; b++) {
        gemm_tc<<<dim3(4, 16, 16), 256, SMEM>>>(
            pf + (long long)b * CH * CS * CS, CS, (long long)CS * CS,
            kt + (long long)b * 512 * 2048, 2048, 0,
            oc + (long long)b * CS * 8192, 8192, 512,
            2048, 512, 2048, 0, 1, 1);
    }
    // 12) o_v per head: oc[:,h*512:+512] @ w_v[h] -> ov[:,h*128:+128] (rounded)
    gemm_tc<<<dim3(1, 32, 16), 256, SMEM>>>(oc, 8192, 512, wvr, 512, 65536,
        ov, 2048, 128, 4096, 128, 512, 0, 0, 1);
    // 13) out = ov @ wo^T (full fp32 out)
    gemm_tc<<<dim3(16, 32, 1), 256, SMEM>>>(ov, 2048, 0, wor, 2048, 0,
        out, 2048, 0, 4096, 2048, 2048, 0, 0, 0);
}